// round 15
// baseline (speedup 1.0000x reference)
#include <cuda_runtime.h>
#include <cstdint>

// Problem dims (fixed)
#define TOK   8192      // B*N
#define DIM   1024      // D
#define NCB   64        // C codebooks
#define KD    16        // K
#define NP    64        // P keys
#define MV    128       // M
#define NR    8         // R
#define NPROJ 2048      // 2 branches * C*K

// Scratch: proj (64MB) + pre-split tf32 hi/lo operands (80MB)
__device__ float g_proj[(size_t)TOK * NPROJ];
__device__ float g_xh[(size_t)TOK * DIM];
__device__ float g_xl[(size_t)TOK * DIM];
__device__ float g_wh[(size_t)NPROJ * DIM];
__device__ float g_wl[(size_t)NPROJ * DIM];

__device__ __forceinline__ uint32_t f2tf32(float x) {
    uint32_t r;
    asm("cvt.rna.tf32.f32 %0, %1;" : "=r"(r) : "f"(x));
    return r;
}

__device__ __forceinline__ void split4(float4 v, float4& h, float4& l) {
    h.x = __uint_as_float(f2tf32(v.x));
    h.y = __uint_as_float(f2tf32(v.y));
    h.z = __uint_as_float(f2tf32(v.z));
    h.w = __uint_as_float(f2tf32(v.w));
    l.x = __uint_as_float(f2tf32(v.x - h.x));
    l.y = __uint_as_float(f2tf32(v.y - h.y));
    l.z = __uint_as_float(f2tf32(v.z - h.z));
    l.w = __uint_as_float(f2tf32(v.w - h.w));
}

// ===========================================================================
// Kernel 0: one-shot hi/lo split of X and W (removes redundant per-CTA split:
// X was re-split 16x, W 64x inside the GEMM).
// ===========================================================================
#define XQ (TOK * DIM / 4)     // 2097152 float4
#define WQ (NPROJ * DIM / 4)   // 524288 float4 (rows 0-1023: WA, 1024-2047: WB)

__global__ __launch_bounds__(256) void presplit(
    const float* __restrict__ X,
    const float* __restrict__ WA,
    const float* __restrict__ WB)
{
    const int i = blockIdx.x * 256 + threadIdx.x;
    float4 v, h, l;
    if (i < XQ) {
        v = __ldg((const float4*)X + i);
        split4(v, h, l);
        ((float4*)g_xh)[i] = h;
        ((float4*)g_xl)[i] = l;
    } else {
        const int j = i - XQ;               // < WQ
        const int half = WQ / 2;
        v = (j < half) ? __ldg((const float4*)WA + j)
                       : __ldg((const float4*)WB + (j - half));
        split4(v, h, l);
        ((float4*)g_wh)[j] = h;
        ((float4*)g_wl)[j] = l;
    }
}

// ===========================================================================
// Kernel 1: 3xTF32 GEMM via mma.sync.m16n8k8 (layout verified R7/R8/R10/R12).
// R13 (re-bench x2): operands pre-split in gmem; tiles staged via cp.async,
// double-buffered, 2 barriers/chunk.
// ===========================================================================
#define BM 128
#define BN 128
#define BK 16
#define PSTR 20                 // padded row stride (floats)
#define TS (128 * PSTR)         // floats per tile buffer (2560)
#define GEMM_SMEM (2 * 4 * TS * 4)   // 81920 B

__device__ __forceinline__ void mma8(float* c, const uint32_t* a, const uint32_t* b) {
    asm volatile(
        "mma.sync.aligned.m16n8k8.row.col.f32.tf32.tf32.f32 "
        "{%0,%1,%2,%3}, {%4,%5,%6,%7}, {%8,%9}, {%0,%1,%2,%3};"
        : "+f"(c[0]), "+f"(c[1]), "+f"(c[2]), "+f"(c[3])
        : "r"(a[0]), "r"(a[1]), "r"(a[2]), "r"(a[3]), "r"(b[0]), "r"(b[1]));
}

__global__ __launch_bounds__(256, 2) void proj_gemm_mma(float* __restrict__ out)
{
    extern __shared__ float sm[];
    const int tid  = threadIdx.x;
    const int warp = tid >> 5;
    const int lane = tid & 31;
    const int g    = lane >> 2;     // groupID
    const int tg   = lane & 3;      // threadID_in_group
    const int wm   = warp & 3;      // warp row  (4 x 32 rows)
    const int wn   = warp >> 2;     // warp col  (2 x 64 cols)

    const int n0 = blockIdx.x * BN;
    const int t0 = blockIdx.y * BM;

    const uint32_t smem_u = (uint32_t)__cvta_generic_to_shared(sm);

    // cp.async staging: each thread copies 2x16B per tile (4 tiles).
    const int idx0 = tid * 2;
    const int row0 = idx0 >> 2, c0_ = idx0 & 3;
    const int row1 = (idx0 + 1) >> 2, c1_ = (idx0 + 1) & 3;
    const uint32_t d0 = (uint32_t)(row0 * PSTR + c0_ * 4) * 4;
    const uint32_t d1 = (uint32_t)(row1 * PSTR + c1_ * 4) * 4;
    const size_t sa0 = (size_t)(t0 + row0) * DIM + c0_ * 4;
    const size_t sa1 = (size_t)(t0 + row1) * DIM + c1_ * 4;
    const size_t sb0 = (size_t)(n0 + row0) * DIM + c0_ * 4;
    const size_t sb1 = (size_t)(n0 + row1) * DIM + c1_ * 4;

    #define ISSUE_CHUNK(CH, BUF) do {                                        \
        const int k0_ = (CH) * BK;                                           \
        const uint32_t tb = smem_u + (BUF) * 4 * TS * 4;                     \
        asm volatile("cp.async.cg.shared.global [%0], [%1], 16;"             \
            :: "r"(tb + 0*TS*4 + d0), "l"(g_xh + sa0 + k0_));                \
        asm volatile("cp.async.cg.shared.global [%0], [%1], 16;"             \
            :: "r"(tb + 0*TS*4 + d1), "l"(g_xh + sa1 + k0_));                \
        asm volatile("cp.async.cg.shared.global [%0], [%1], 16;"             \
            :: "r"(tb + 1*TS*4 + d0), "l"(g_xl + sa0 + k0_));                \
        asm volatile("cp.async.cg.shared.global [%0], [%1], 16;"             \
            :: "r"(tb + 1*TS*4 + d1), "l"(g_xl + sa1 + k0_));                \
        asm volatile("cp.async.cg.shared.global [%0], [%1], 16;"             \
            :: "r"(tb + 2*TS*4 + d0), "l"(g_wh + sb0 + k0_));                \
        asm volatile("cp.async.cg.shared.global [%0], [%1], 16;"             \
            :: "r"(tb + 2*TS*4 + d1), "l"(g_wh + sb1 + k0_));                \
        asm volatile("cp.async.cg.shared.global [%0], [%1], 16;"             \
            :: "r"(tb + 3*TS*4 + d0), "l"(g_wl + sb0 + k0_));                \
        asm volatile("cp.async.cg.shared.global [%0], [%1], 16;"             \
            :: "r"(tb + 3*TS*4 + d1), "l"(g_wl + sb1 + k0_));                \
        asm volatile("cp.async.commit_group;");                              \
    } while (0)

    float acc[2][8][4];
    #pragma unroll
    for (int mi = 0; mi < 2; mi++)
        #pragma unroll
        for (int ni = 0; ni < 8; ni++)
            #pragma unroll
            for (int q = 0; q < 4; q++) acc[mi][ni][q] = 0.f;

    const int NCHUNK_G = DIM / BK;   // 64
    ISSUE_CHUNK(0, 0);

    for (int ch = 0; ch < NCHUNK_G; ch++) {
        if (ch + 1 < NCHUNK_G) {
            ISSUE_CHUNK(ch + 1, (ch + 1) & 1);
            asm volatile("cp.async.wait_group 1;");
        } else {
            asm volatile("cp.async.wait_group 0;");
        }
        __syncthreads();

        const float* AH = sm + ((ch & 1) * 4 + 0) * TS;
        const float* AL = sm + ((ch & 1) * 4 + 1) * TS;
        const float* BH = sm + ((ch & 1) * 4 + 2) * TS;
        const float* BL = sm + ((ch & 1) * 4 + 3) * TS;

        #pragma unroll
        for (int kk = 0; kk < 2; kk++) {
            const int kc = kk * 8 + tg;

            uint32_t ah[2][4], al[2][4];
            #pragma unroll
            for (int mi = 0; mi < 2; mi++) {
                const int r0 = (wm * 32 + mi * 16 + g) * PSTR;
                ah[mi][0] = __float_as_uint(AH[r0 + kc]);
                ah[mi][1] = __float_as_uint(AH[r0 + 8 * PSTR + kc]);
                ah[mi][2] = __float_as_uint(AH[r0 + kc + 4]);
                ah[mi][3] = __float_as_uint(AH[r0 + 8 * PSTR + kc + 4]);
                al[mi][0] = __float_as_uint(AL[r0 + kc]);
                al[mi][1] = __float_as_uint(AL[r0 + 8 * PSTR + kc]);
                al[mi][2] = __float_as_uint(AL[r0 + kc + 4]);
                al[mi][3] = __float_as_uint(AL[r0 + 8 * PSTR + kc + 4]);
            }
            uint32_t bh[8][2], bl[8][2];
            #pragma unroll
            for (int ni = 0; ni < 8; ni++) {
                const int nb = (wn * 64 + ni * 8 + g) * PSTR;
                bh[ni][0] = __float_as_uint(BH[nb + kc]);
                bh[ni][1] = __float_as_uint(BH[nb + kc + 4]);
                bl[ni][0] = __float_as_uint(BL[nb + kc]);
                bl[ni][1] = __float_as_uint(BL[nb + kc + 4]);
            }

            #pragma unroll
            for (int mi = 0; mi < 2; mi++)
                #pragma unroll
                for (int ni = 0; ni < 8; ni++)
                    mma8(acc[mi][ni], ah[mi], bh[ni]);   // hh
            #pragma unroll
            for (int mi = 0; mi < 2; mi++)
                #pragma unroll
                for (int ni = 0; ni < 8; ni++)
                    mma8(acc[mi][ni], ah[mi], bl[ni]);   // hl
            #pragma unroll
            for (int mi = 0; mi < 2; mi++)
                #pragma unroll
                for (int ni = 0; ni < 8; ni++)
                    mma8(acc[mi][ni], al[mi], bh[ni]);   // lh
        }
        __syncthreads();   // buffer (ch&1) free before it is re-issued at ch+2
    }

    #pragma unroll
    for (int mi = 0; mi < 2; mi++) {
        const int row = t0 + wm * 32 + mi * 16 + g;
        #pragma unroll
        for (int ni = 0; ni < 8; ni++) {
            const int col = n0 + wn * 64 + ni * 8 + tg * 2;
            *(float2*)(out + (size_t)row * NPROJ + col)
                = make_float2(acc[mi][ni][0], acc[mi][ni][1]);
            *(float2*)(out + (size_t)(row + 8) * NPROJ + col)
                = make_float2(acc[mi][ni][2], acc[mi][ni][3]);
        }
    }
}

// ---------------------------------------------------------------------------
// Kernel 2: fused argmin + gather-dot + output, margin-gated fp32 refine.
// R13 (re-bench x2): 32-bit packed (ord&~63 | idx) + single REDUX min
// replaces the 64-bit shuffle tree; sub-ULP mis-picks fall inside the gate.
// ---------------------------------------------------------------------------
#define GTOK 8
#define FUSE_SMEM (GTOK * NPROJ * 4)   // 64 KB dynamic
#define REFINE_TH 0.002f

__device__ __forceinline__ unsigned ord_f32(float f) {
    unsigned b = __float_as_uint(f);
    return (b & 0x80000000u) ? ~b : (b | 0x80000000u);  // monotonic map
}

__device__ __forceinline__ float inv_ord(unsigned u) {
    unsigned b = (u & 0x80000000u) ? (u ^ 0x80000000u) : ~u;
    return __uint_as_float(b);
}

__global__ __launch_bounds__(256) void fuse_kernel(
    const float* __restrict__ x,
    const float* __restrict__ proj,
    const float* __restrict__ W_A_, const float* __restrict__ W_B_,
    const float* __restrict__ emb_A, const float* __restrict__ vals_A,
    const float* __restrict__ emb_B, const float* __restrict__ vals_B,
    float* __restrict__ out)
{
    extern __shared__ float proj_s[];            // GTOK*2048 floats
    __shared__ float sA[GTOK * NCB];
    __shared__ float tb[GTOK * NR];
    __shared__ int   idxA[GTOK * NCB];
    __shared__ int   idxB[GTOK * NCB];

    const int tid  = threadIdx.x;
    const int warp = tid >> 5;
    const int lane = tid & 31;
    const int tok0 = blockIdx.x * GTOK;

    // ---- stage proj via cp.async ----
    {
        const float* src = proj + (size_t)tok0 * NPROJ;
        unsigned sdst = (unsigned)__cvta_generic_to_shared(proj_s);
        #pragma unroll
        for (int i = tid; i < GTOK * NPROJ / 4; i += 256) {
            asm volatile("cp.async.cg.shared.global [%0], [%1], 16;"
                         :: "r"(sdst + i * 16), "l"(src + i * 4));
        }
        asm volatile("cp.async.commit_group;");
        asm volatile("cp.async.wait_group 0;");
    }
    __syncthreads();

    // ---- distance + argmin: 128 (branch, codebook) pairs over 8 warps ----
    for (int pair = warp; pair < 2 * NCB; pair += 8) {
        const int br = pair >> 6;
        const int c  = pair & 63;
        const float* emb = br ? emb_B : emb_A;
        float e0[KD], e1[KD];
        {
            const float4* r0 = (const float4*)(emb + ((size_t)c * NP + lane) * KD);
            const float4* r1 = r0 + 32 * KD / 4;
            #pragma unroll
            for (int q = 0; q < 4; q++) {
                float4 v0 = __ldg(r0 + q), v1 = __ldg(r1 + q);
                e0[q*4+0]=v0.x; e0[q*4+1]=v0.y; e0[q*4+2]=v0.z; e0[q*4+3]=v0.w;
                e1[q*4+0]=v1.x; e1[q*4+1]=v1.y; e1[q*4+2]=v1.z; e1[q*4+3]=v1.w;
            }
        }
        float ee0 = 0.f, ee1 = 0.f;
        #pragma unroll
        for (int k = 0; k < KD; k++) { ee0 = fmaf(e0[k], e0[k], ee0); ee1 = fmaf(e1[k], e1[k], ee1); }

        #pragma unroll
        for (int g2 = 0; g2 < GTOK; g2++) {
            const float4* pr = (const float4*)(proj_s + g2 * NPROJ + br * 1024 + c * KD);
            float p[KD];
            #pragma unroll
            for (int q = 0; q < 4; q++) {
                float4 v = pr[q];   // broadcast LDS.128
                p[q*4+0]=v.x; p[q*4+1]=v.y; p[q*4+2]=v.z; p[q*4+3]=v.w;
            }
            float pp = 0.f, d0 = 0.f, d1 = 0.f;
            #pragma unroll
            for (int k = 0; k < KD; k++) {
                pp = fmaf(p[k], p[k], pp);
                d0 = fmaf(p[k], e0[k], d0);
                d1 = fmaf(p[k], e1[k], d1);
            }
            float s0 = (pp - 2.0f * d0) + ee0;
            float s1 = (pp - 2.0f * d1) + ee1;

            // 32-bit packed lexicographic min via REDUX
            unsigned q0 = (ord_f32(s0) & 0xFFFFFFC0u) | (unsigned)lane;
            unsigned q1 = (ord_f32(s1) & 0xFFFFFFC0u) | (unsigned)(lane + 32);
            unsigned qm = (q1 < q0) ? q1 : q0;
            qm = __reduce_min_sync(0xffffffffu, qm);

            // gate: any non-winner score within TH of the (rounded-down) min?
            const float smin = inv_ord(qm & 0xFFFFFFC0u);
            const int winner = (int)(qm & 63u);
            bool c0 = (s0 - smin < REFINE_TH) && (lane != winner);
            bool c1 = (s1 - smin < REFINE_TH) && (lane + 32 != winner);
            unsigned need = __ballot_sync(0xffffffffu, c0) | __ballot_sync(0xffffffffu, c1);

            int result = winner;
            if (need) {
                // exact fp32 refine: recompute 16-dim projection x . W[c]
                // lanes 2k,2k+1 jointly compute proj_k
                const float* wrow = (br ? W_B_ : W_A_)
                                  + ((size_t)c * KD + (lane >> 1)) * DIM;
                const float* xrow = x + (size_t)(tok0 + g2) * DIM;
                float acc0 = 0.f, acc1 = 0.f;
                #pragma unroll 2
                for (int d = (lane & 1) * 4; d < DIM; d += 16) {
                    float4 wv = __ldg((const float4*)(wrow + d));
                    float4 xv = *(const float4*)(xrow + d);
                    float4 wv2 = __ldg((const float4*)(wrow + d + 8));
                    float4 xv2 = *(const float4*)(xrow + d + 8);
                    acc0 = fmaf(wv.x, xv.x, acc0);
                    acc0 = fmaf(wv.y, xv.y, acc0);
                    acc0 = fmaf(wv.z, xv.z, acc0);
                    acc0 = fmaf(wv.w, xv.w, acc0);
                    acc1 = fmaf(wv2.x, xv2.x, acc1);
                    acc1 = fmaf(wv2.y, xv2.y, acc1);
                    acc1 = fmaf(wv2.z, xv2.z, acc1);
                    acc1 = fmaf(wv2.w, xv2.w, acc1);
                }
                float accp = acc0 + acc1;
                accp += __shfl_xor_sync(0xffffffffu, accp, 1);
                float pr2[KD];
                #pragma unroll
                for (int k = 0; k < KD; k++)
                    pr2[k] = __shfl_sync(0xffffffffu, accp, k * 2);
                float pp2 = 0.f, d0r = 0.f, d1r = 0.f;
                #pragma unroll
                for (int k = 0; k < KD; k++) {
                    pp2 = fmaf(pr2[k], pr2[k], pp2);
                    d0r = fmaf(pr2[k], e0[k], d0r);
                    d1r = fmaf(pr2[k], e1[k], d1r);
                }
                float r0s = (pp2 - 2.0f * d0r) + ee0;
                float r1s = (pp2 - 2.0f * d1r) + ee1;
                unsigned long long rk0 = ((unsigned long long)ord_f32(r0s) << 6) | (unsigned)lane;
                unsigned long long rk1 = ((unsigned long long)ord_f32(r1s) << 6) | (unsigned)(lane + 32);
                unsigned long long key = (rk1 < rk0) ? rk1 : rk0;
                #pragma unroll
                for (int off = 16; off > 0; off >>= 1) {
                    unsigned long long o = __shfl_xor_sync(0xffffffffu, key, off);
                    if (o < key) key = o;
                }
                result = (int)(key & 63u);
            }

            if (lane == 0) (br ? idxB : idxA)[g2 * NCB + c] = result;
        }
    }
    __syncthreads();

    // ---- sA: warp per (token, chunk); x-chunk in regs, 8x reuse over c ----
    for (int task = warp; task < GTOK * 8; task += 8) {
        const int g2 = task >> 3, chunk = task & 7;
        float4 xr = *(const float4*)(x + (size_t)(tok0 + g2) * DIM + chunk * MV + lane * 4);
        float acc[8];
        #pragma unroll
        for (int ci = 0; ci < 8; ci++) {
            const int c = ci * 8 + chunk;
            const int id = idxA[g2 * NCB + c];
            float4 vr = __ldg((const float4*)(vals_A + ((size_t)c * NP + id) * MV) + lane);
            acc[ci] = xr.x*vr.x + xr.y*vr.y + xr.z*vr.z + xr.w*vr.w;
        }
        #pragma unroll
        for (int off = 16; off > 0; off >>= 1)
            #pragma unroll
            for (int ci = 0; ci < 8; ci++)
                acc[ci] += __shfl_xor_sync(0xffffffffu, acc[ci], off);
        if (lane == 0) {
            #pragma unroll
            for (int ci = 0; ci < 8; ci++)
                sA[g2 * NCB + ci * 8 + chunk] = acc[ci];
        }
    }
    __syncthreads();

    // ---- t[g][r] = sum of 8 consecutive s ----
    if (tid < GTOK * NR) {
        const int g2 = tid >> 3, r = tid & 7;
        float acc = 0.f;
        #pragma unroll
        for (int i = 0; i < 8; i++) acc += sA[g2 * NCB + r * 8 + i];
        tb[g2 * NR + r] = acc;
    }
    __syncthreads();

    // ---- out[token][h*128+m] = sum_r t[r] * vals_B[8r+h, idxB[8r+h], m] ----
    for (int g2 = 0; g2 < GTOK; g2++) {
        float tr[NR];
        #pragma unroll
        for (int r = 0; r < NR; r++) tr[r] = tb[g2 * NR + r];
        float* orow = out + (size_t)(tok0 + g2) * DIM;
        #pragma unroll
        for (int j = 0; j < 4; j++) {
            const int d = tid + 256 * j;
            const int h = d >> 7, m = d & 127;
            float acc = 0.f;
            #pragma unroll
            for (int r = 0; r < NR; r++) {
                const int c = 8 * r + h;
                acc = fmaf(tr[r],
                           __ldg(vals_B + ((size_t)c * NP + idxB[g2 * NCB + c]) * MV + m),
                           acc);
            }
            orow[d] = acc;
        }
    }
}

// ---------------------------------------------------------------------------
extern "C" void kernel_launch(void* const* d_in, const int* in_sizes, int n_in,
                              void* d_out, int out_size)
{
    (void)in_sizes; (void)n_in; (void)out_size;
    const float* x      = (const float*)d_in[0];
    const float* W_A    = (const float*)d_in[1];
    const float* emb_A  = (const float*)d_in[2];
    const float* vals_A = (const float*)d_in[3];
    const float* W_B    = (const float*)d_in[4];
    const float* emb_B  = (const float*)d_in[5];
    const float* vals_B = (const float*)d_in[6];
    float* out = (float*)d_out;

    float* proj;
    cudaGetSymbolAddress((void**)&proj, g_proj);

    static bool attr_set = false;
    if (!attr_set) {
        cudaFuncSetAttribute(proj_gemm_mma,
                             cudaFuncAttributeMaxDynamicSharedMemorySize, GEMM_SMEM);
        cudaFuncSetAttribute(fuse_kernel,
                             cudaFuncAttributeMaxDynamicSharedMemorySize, FUSE_SMEM);
        attr_set = true;
    }

    presplit<<<(XQ + WQ) / 256, 256>>>(x, W_A, W_B);
    dim3 gg(NPROJ / BN, TOK / BM);   // (16, 64)
    proj_gemm_mma<<<gg, 256, GEMM_SMEM>>>(proj);
    fuse_kernel<<<TOK / GTOK, 256, FUSE_SMEM>>>(x, proj, W_A, W_B,
                                                emb_A, vals_A, emb_B, vals_B, out);
}

// round 16
// speedup vs baseline: 1.1717x; 1.1717x over previous
#include <cuda_runtime.h>
#include <cstdint>

// Problem dims (fixed)
#define TOK   8192      // B*N
#define DIM   1024      // D
#define NCB   64        // C codebooks
#define KD    16        // K
#define NP    64        // P keys
#define MV    128       // M
#define NR    8         // R
#define NPROJ 2048      // 2 branches * C*K

// 64 MB scratch for projections
__device__ float g_proj[(size_t)TOK * NPROJ];

// ===========================================================================
// Kernel 1: 3xTF32 GEMM via mma.sync.m16n8k8 — exact R12 version (549 us).
// In-kernel hi/lo split keeps the streamed operands at fp32 X+W = 40 MB,
// which is L2-resident (the R13 pre-split 80 MB variant thrashed L2: -130us).
// ===========================================================================
#define BM 128
#define BN 128
#define BK 16
#define PSTR 20                 // padded row stride (floats)
#define TS (128 * PSTR)         // floats per tile buffer (2560)
#define GEMM_SMEM (2 * 4 * TS * 4)   // 81920 B

__device__ __forceinline__ uint32_t f2tf32(float x) {
    uint32_t r;
    asm("cvt.rna.tf32.f32 %0, %1;" : "=r"(r) : "f"(x));
    return r;
}

__device__ __forceinline__ void split4(float4 v, float4& h, float4& l) {
    h.x = __uint_as_float(f2tf32(v.x));
    h.y = __uint_as_float(f2tf32(v.y));
    h.z = __uint_as_float(f2tf32(v.z));
    h.w = __uint_as_float(f2tf32(v.w));
    l.x = __uint_as_float(f2tf32(v.x - h.x));
    l.y = __uint_as_float(f2tf32(v.y - h.y));
    l.z = __uint_as_float(f2tf32(v.z - h.z));
    l.w = __uint_as_float(f2tf32(v.w - h.w));
}

__device__ __forceinline__ void mma8(float* c, const uint32_t* a, const uint32_t* b) {
    asm volatile(
        "mma.sync.aligned.m16n8k8.row.col.f32.tf32.tf32.f32 "
        "{%0,%1,%2,%3}, {%4,%5,%6,%7}, {%8,%9}, {%0,%1,%2,%3};"
        : "+f"(c[0]), "+f"(c[1]), "+f"(c[2]), "+f"(c[3])
        : "r"(a[0]), "r"(a[1]), "r"(a[2]), "r"(a[3]), "r"(b[0]), "r"(b[1]));
}

__global__ __launch_bounds__(256, 2) void proj_gemm_mma(
    const float* __restrict__ X,
    const float* __restrict__ WA,
    const float* __restrict__ WB,
    float* __restrict__ out)
{
    extern __shared__ float sm[];
    const int tid  = threadIdx.x;
    const int warp = tid >> 5;
    const int lane = tid & 31;
    const int g    = lane >> 2;     // groupID
    const int tg   = lane & 3;      // threadID_in_group
    const int wm   = warp & 3;      // warp row  (4 x 32 rows)
    const int wn   = warp >> 2;     // warp col  (2 x 64 cols)

    const int n0 = blockIdx.x * BN;
    const int t0 = blockIdx.y * BM;
    const float* __restrict__ Wbase = (n0 < 1024) ? (WA + (size_t)n0 * DIM)
                                                  : (WB + (size_t)(n0 - 1024) * DIM);

    const int rowL = tid >> 2;
    const int c4   = tid & 3;
    const float* aSrc0 = X     + (size_t)(t0 + rowL) * DIM + c4 * 4;
    const float* aSrc1 = aSrc0 + (size_t)64 * DIM;
    const float* bSrc0 = Wbase + (size_t)rowL        * DIM + c4 * 4;
    const float* bSrc1 = bSrc0 + (size_t)64 * DIM;
    const int sOff0 = rowL * PSTR + c4 * 4;
    const int sOff1 = (rowL + 64) * PSTR + c4 * 4;

    float acc[2][8][4];
    #pragma unroll
    for (int mi = 0; mi < 2; mi++)
        #pragma unroll
        for (int ni = 0; ni < 8; ni++)
            #pragma unroll
            for (int q = 0; q < 4; q++) acc[mi][ni][q] = 0.f;

    float4 a0 = *(const float4*)(aSrc0);
    float4 a1 = *(const float4*)(aSrc1);
    float4 b0 = *(const float4*)(bSrc0);
    float4 b1 = *(const float4*)(bSrc1);

    const int NCHUNK_G = DIM / BK;   // 64
    for (int ch = 0; ch < NCHUNK_G; ch++) {
        float* AH = sm + ((ch & 1) * 4 + 0) * TS;
        float* AL = sm + ((ch & 1) * 4 + 1) * TS;
        float* BH = sm + ((ch & 1) * 4 + 2) * TS;
        float* BL = sm + ((ch & 1) * 4 + 3) * TS;

        {
            float4 h, l;
            split4(a0, h, l); *(float4*)(AH + sOff0) = h; *(float4*)(AL + sOff0) = l;
            split4(a1, h, l); *(float4*)(AH + sOff1) = h; *(float4*)(AL + sOff1) = l;
            split4(b0, h, l); *(float4*)(BH + sOff0) = h; *(float4*)(BL + sOff0) = l;
            split4(b1, h, l); *(float4*)(BH + sOff1) = h; *(float4*)(BL + sOff1) = l;
        }
        __syncthreads();

        if (ch < NCHUNK_G - 1) {
            const int k1 = (ch + 1) * BK;
            a0 = *(const float4*)(aSrc0 + k1);
            a1 = *(const float4*)(aSrc1 + k1);
            b0 = *(const float4*)(bSrc0 + k1);
            b1 = *(const float4*)(bSrc1 + k1);
        }

        #pragma unroll
        for (int kk = 0; kk < 2; kk++) {
            const int kc = kk * 8 + tg;

            uint32_t ah[2][4], al[2][4];
            #pragma unroll
            for (int mi = 0; mi < 2; mi++) {
                const int r0 = (wm * 32 + mi * 16 + g) * PSTR;
                ah[mi][0] = __float_as_uint(AH[r0 + kc]);
                ah[mi][1] = __float_as_uint(AH[r0 + 8 * PSTR + kc]);
                ah[mi][2] = __float_as_uint(AH[r0 + kc + 4]);
                ah[mi][3] = __float_as_uint(AH[r0 + 8 * PSTR + kc + 4]);
                al[mi][0] = __float_as_uint(AL[r0 + kc]);
                al[mi][1] = __float_as_uint(AL[r0 + 8 * PSTR + kc]);
                al[mi][2] = __float_as_uint(AL[r0 + kc + 4]);
                al[mi][3] = __float_as_uint(AL[r0 + 8 * PSTR + kc + 4]);
            }
            uint32_t bh[8][2], bl[8][2];
            #pragma unroll
            for (int ni = 0; ni < 8; ni++) {
                const int nb = (wn * 64 + ni * 8 + g) * PSTR;
                bh[ni][0] = __float_as_uint(BH[nb + kc]);
                bh[ni][1] = __float_as_uint(BH[nb + kc + 4]);
                bl[ni][0] = __float_as_uint(BL[nb + kc]);
                bl[ni][1] = __float_as_uint(BL[nb + kc + 4]);
            }

            #pragma unroll
            for (int mi = 0; mi < 2; mi++)
                #pragma unroll
                for (int ni = 0; ni < 8; ni++)
                    mma8(acc[mi][ni], ah[mi], bh[ni]);   // hh
            #pragma unroll
            for (int mi = 0; mi < 2; mi++)
                #pragma unroll
                for (int ni = 0; ni < 8; ni++)
                    mma8(acc[mi][ni], ah[mi], bl[ni]);   // hl
            #pragma unroll
            for (int mi = 0; mi < 2; mi++)
                #pragma unroll
                for (int ni = 0; ni < 8; ni++)
                    mma8(acc[mi][ni], al[mi], bh[ni]);   // lh
        }
    }

    #pragma unroll
    for (int mi = 0; mi < 2; mi++) {
        const int row = t0 + wm * 32 + mi * 16 + g;
        #pragma unroll
        for (int ni = 0; ni < 8; ni++) {
            const int col = n0 + wn * 64 + ni * 8 + tg * 2;
            *(float2*)(out + (size_t)row * NPROJ + col)
                = make_float2(acc[mi][ni][0], acc[mi][ni][1]);
            *(float2*)(out + (size_t)(row + 8) * NPROJ + col)
                = make_float2(acc[mi][ni][2], acc[mi][ni][3]);
        }
    }
}

// ---------------------------------------------------------------------------
// Kernel 2: fused argmin + gather-dot + output, margin-gated fp32 refine.
// R16 keeps the R13 REDUX argmin: 32-bit packed (ord&~63 | idx) + single
// __reduce_min_sync; sub-ULP mis-picks fall inside the gate -> fp32 refined.
// ---------------------------------------------------------------------------
#define GTOK 8
#define FUSE_SMEM (GTOK * NPROJ * 4)   // 64 KB dynamic
#define REFINE_TH 0.002f

__device__ __forceinline__ unsigned ord_f32(float f) {
    unsigned b = __float_as_uint(f);
    return (b & 0x80000000u) ? ~b : (b | 0x80000000u);  // monotonic map
}

__device__ __forceinline__ float inv_ord(unsigned u) {
    unsigned b = (u & 0x80000000u) ? (u ^ 0x80000000u) : ~u;
    return __uint_as_float(b);
}

__global__ __launch_bounds__(256) void fuse_kernel(
    const float* __restrict__ x,
    const float* __restrict__ proj,
    const float* __restrict__ W_A_, const float* __restrict__ W_B_,
    const float* __restrict__ emb_A, const float* __restrict__ vals_A,
    const float* __restrict__ emb_B, const float* __restrict__ vals_B,
    float* __restrict__ out)
{
    extern __shared__ float proj_s[];            // GTOK*2048 floats
    __shared__ float sA[GTOK * NCB];
    __shared__ float tb[GTOK * NR];
    __shared__ int   idxA[GTOK * NCB];
    __shared__ int   idxB[GTOK * NCB];

    const int tid  = threadIdx.x;
    const int warp = tid >> 5;
    const int lane = tid & 31;
    const int tok0 = blockIdx.x * GTOK;

    // ---- stage proj via cp.async ----
    {
        const float* src = proj + (size_t)tok0 * NPROJ;
        unsigned sdst = (unsigned)__cvta_generic_to_shared(proj_s);
        #pragma unroll
        for (int i = tid; i < GTOK * NPROJ / 4; i += 256) {
            asm volatile("cp.async.cg.shared.global [%0], [%1], 16;"
                         :: "r"(sdst + i * 16), "l"(src + i * 4));
        }
        asm volatile("cp.async.commit_group;");
        asm volatile("cp.async.wait_group 0;");
    }
    __syncthreads();

    // ---- distance + argmin: 128 (branch, codebook) pairs over 8 warps ----
    for (int pair = warp; pair < 2 * NCB; pair += 8) {
        const int br = pair >> 6;
        const int c  = pair & 63;
        const float* emb = br ? emb_B : emb_A;
        float e0[KD], e1[KD];
        {
            const float4* r0 = (const float4*)(emb + ((size_t)c * NP + lane) * KD);
            const float4* r1 = r0 + 32 * KD / 4;
            #pragma unroll
            for (int q = 0; q < 4; q++) {
                float4 v0 = __ldg(r0 + q), v1 = __ldg(r1 + q);
                e0[q*4+0]=v0.x; e0[q*4+1]=v0.y; e0[q*4+2]=v0.z; e0[q*4+3]=v0.w;
                e1[q*4+0]=v1.x; e1[q*4+1]=v1.y; e1[q*4+2]=v1.z; e1[q*4+3]=v1.w;
            }
        }
        float ee0 = 0.f, ee1 = 0.f;
        #pragma unroll
        for (int k = 0; k < KD; k++) { ee0 = fmaf(e0[k], e0[k], ee0); ee1 = fmaf(e1[k], e1[k], ee1); }

        #pragma unroll
        for (int g2 = 0; g2 < GTOK; g2++) {
            const float4* pr = (const float4*)(proj_s + g2 * NPROJ + br * 1024 + c * KD);
            float p[KD];
            #pragma unroll
            for (int q = 0; q < 4; q++) {
                float4 v = pr[q];   // broadcast LDS.128
                p[q*4+0]=v.x; p[q*4+1]=v.y; p[q*4+2]=v.z; p[q*4+3]=v.w;
            }
            float pp = 0.f, d0 = 0.f, d1 = 0.f;
            #pragma unroll
            for (int k = 0; k < KD; k++) {
                pp = fmaf(p[k], p[k], pp);
                d0 = fmaf(p[k], e0[k], d0);
                d1 = fmaf(p[k], e1[k], d1);
            }
            float s0 = (pp - 2.0f * d0) + ee0;
            float s1 = (pp - 2.0f * d1) + ee1;

            // 32-bit packed lexicographic min via REDUX
            unsigned q0 = (ord_f32(s0) & 0xFFFFFFC0u) | (unsigned)lane;
            unsigned q1 = (ord_f32(s1) & 0xFFFFFFC0u) | (unsigned)(lane + 32);
            unsigned qm = (q1 < q0) ? q1 : q0;
            qm = __reduce_min_sync(0xffffffffu, qm);

            // gate: any non-winner score within TH of the (rounded-down) min?
            const float smin = inv_ord(qm & 0xFFFFFFC0u);
            const int winner = (int)(qm & 63u);
            bool c0 = (s0 - smin < REFINE_TH) && (lane != winner);
            bool c1 = (s1 - smin < REFINE_TH) && (lane + 32 != winner);
            unsigned need = __ballot_sync(0xffffffffu, c0) | __ballot_sync(0xffffffffu, c1);

            int result = winner;
            if (need) {
                // exact fp32 refine: recompute 16-dim projection x . W[c]
                // lanes 2k,2k+1 jointly compute proj_k
                const float* wrow = (br ? W_B_ : W_A_)
                                  + ((size_t)c * KD + (lane >> 1)) * DIM;
                const float* xrow = x + (size_t)(tok0 + g2) * DIM;
                float acc0 = 0.f, acc1 = 0.f;
                #pragma unroll 2
                for (int d = (lane & 1) * 4; d < DIM; d += 16) {
                    float4 wv = __ldg((const float4*)(wrow + d));
                    float4 xv = *(const float4*)(xrow + d);
                    float4 wv2 = __ldg((const float4*)(wrow + d + 8));
                    float4 xv2 = *(const float4*)(xrow + d + 8);
                    acc0 = fmaf(wv.x, xv.x, acc0);
                    acc0 = fmaf(wv.y, xv.y, acc0);
                    acc0 = fmaf(wv.z, xv.z, acc0);
                    acc0 = fmaf(wv.w, xv.w, acc0);
                    acc1 = fmaf(wv2.x, xv2.x, acc1);
                    acc1 = fmaf(wv2.y, xv2.y, acc1);
                    acc1 = fmaf(wv2.z, xv2.z, acc1);
                    acc1 = fmaf(wv2.w, xv2.w, acc1);
                }
                float accp = acc0 + acc1;
                accp += __shfl_xor_sync(0xffffffffu, accp, 1);
                float pr2[KD];
                #pragma unroll
                for (int k = 0; k < KD; k++)
                    pr2[k] = __shfl_sync(0xffffffffu, accp, k * 2);
                float pp2 = 0.f, d0r = 0.f, d1r = 0.f;
                #pragma unroll
                for (int k = 0; k < KD; k++) {
                    pp2 = fmaf(pr2[k], pr2[k], pp2);
                    d0r = fmaf(pr2[k], e0[k], d0r);
                    d1r = fmaf(pr2[k], e1[k], d1r);
                }
                float r0s = (pp2 - 2.0f * d0r) + ee0;
                float r1s = (pp2 - 2.0f * d1r) + ee1;
                unsigned long long rk0 = ((unsigned long long)ord_f32(r0s) << 6) | (unsigned)lane;
                unsigned long long rk1 = ((unsigned long long)ord_f32(r1s) << 6) | (unsigned)(lane + 32);
                unsigned long long key = (rk1 < rk0) ? rk1 : rk0;
                #pragma unroll
                for (int off = 16; off > 0; off >>= 1) {
                    unsigned long long o = __shfl_xor_sync(0xffffffffu, key, off);
                    if (o < key) key = o;
                }
                result = (int)(key & 63u);
            }

            if (lane == 0) (br ? idxB : idxA)[g2 * NCB + c] = result;
        }
    }
    __syncthreads();

    // ---- sA: warp per (token, chunk); x-chunk in regs, 8x reuse over c ----
    for (int task = warp; task < GTOK * 8; task += 8) {
        const int g2 = task >> 3, chunk = task & 7;
        float4 xr = *(const float4*)(x + (size_t)(tok0 + g2) * DIM + chunk * MV + lane * 4);
        float acc[8];
        #pragma unroll
        for (int ci = 0; ci < 8; ci++) {
            const int c = ci * 8 + chunk;
            const int id = idxA[g2 * NCB + c];
            float4 vr = __ldg((const float4*)(vals_A + ((size_t)c * NP + id) * MV) + lane);
            acc[ci] = xr.x*vr.x + xr.y*vr.y + xr.z*vr.z + xr.w*vr.w;
        }
        #pragma unroll
        for (int off = 16; off > 0; off >>= 1)
            #pragma unroll
            for (int ci = 0; ci < 8; ci++)
                acc[ci] += __shfl_xor_sync(0xffffffffu, acc[ci], off);
        if (lane == 0) {
            #pragma unroll
            for (int ci = 0; ci < 8; ci++)
                sA[g2 * NCB + ci * 8 + chunk] = acc[ci];
        }
    }
    __syncthreads();

    // ---- t[g][r] = sum of 8 consecutive s ----
    if (tid < GTOK * NR) {
        const int g2 = tid >> 3, r = tid & 7;
        float acc = 0.f;
        #pragma unroll
        for (int i = 0; i < 8; i++) acc += sA[g2 * NCB + r * 8 + i];
        tb[g2 * NR + r] = acc;
    }
    __syncthreads();

    // ---- out[token][h*128+m] = sum_r t[r] * vals_B[8r+h, idxB[8r+h], m] ----
    for (int g2 = 0; g2 < GTOK; g2++) {
        float tr[NR];
        #pragma unroll
        for (int r = 0; r < NR; r++) tr[r] = tb[g2 * NR + r];
        float* orow = out + (size_t)(tok0 + g2) * DIM;
        #pragma unroll
        for (int j = 0; j < 4; j++) {
            const int d = tid + 256 * j;
            const int h = d >> 7, m = d & 127;
            float acc = 0.f;
            #pragma unroll
            for (int r = 0; r < NR; r++) {
                const int c = 8 * r + h;
                acc = fmaf(tr[r],
                           __ldg(vals_B + ((size_t)c * NP + idxB[g2 * NCB + c]) * MV + m),
                           acc);
            }
            orow[d] = acc;
        }
    }
}

// ---------------------------------------------------------------------------
extern "C" void kernel_launch(void* const* d_in, const int* in_sizes, int n_in,
                              void* d_out, int out_size)
{
    (void)in_sizes; (void)n_in; (void)out_size;
    const float* x      = (const float*)d_in[0];
    const float* W_A    = (const float*)d_in[1];
    const float* emb_A  = (const float*)d_in[2];
    const float* vals_A = (const float*)d_in[3];
    const float* W_B    = (const float*)d_in[4];
    const float* emb_B  = (const float*)d_in[5];
    const float* vals_B = (const float*)d_in[6];
    float* out = (float*)d_out;

    float* proj;
    cudaGetSymbolAddress((void**)&proj, g_proj);

    static bool attr_set = false;
    if (!attr_set) {
        cudaFuncSetAttribute(proj_gemm_mma,
                             cudaFuncAttributeMaxDynamicSharedMemorySize, GEMM_SMEM);
        cudaFuncSetAttribute(fuse_kernel,
                             cudaFuncAttributeMaxDynamicSharedMemorySize, FUSE_SMEM);
        attr_set = true;
    }

    dim3 gg(NPROJ / BN, TOK / BM);   // (16, 64)
    proj_gemm_mma<<<gg, 256, GEMM_SMEM>>>(x, W_A, W_B, proj);
    fuse_kernel<<<TOK / GTOK, 256, FUSE_SMEM>>>(x, proj, W_A, W_B,
                                                emb_A, vals_A, emb_B, vals_B, out);
}

// round 17
// speedup vs baseline: 1.5939x; 1.3603x over previous
#include <cuda_runtime.h>
#include <cuda_bf16.h>
#include <cstdint>

// Problem dims (fixed)
#define TOK   8192      // B*N
#define DIM   1024      // D
#define NCB   64        // C codebooks
#define KD    16        // K
#define NP    64        // P keys
#define MV    128       // M
#define NR    8         // R
#define NPROJ 2048      // 2 branches * C*K

// 64 MB scratch for projections
__device__ float g_proj[(size_t)TOK * NPROJ];

// ===========================================================================
// Kernel 1: 3xBF16 GEMM via mma.sync.m16n8k16 (K=16/instr, 2x tf32's K=8).
// D = Ah*Bh + Ah*Bl + Al*Bh, fp32 accum; residual ~2^-18/product -> score
// error ~5e-5, 40x under the refine gate. Streams stay fp32 (L2-resident).
// ===========================================================================
#define BM 128
#define BN 128
#define BK 16
#define PSTRB 48                // bytes per bf16 row (32B data + 16B pad)
#define TSB (128 * PSTRB)       // 6144 B per tile
#define GEMM_SMEM (2 * 4 * TSB) // 49152 B

__device__ __forceinline__ void split_sts_bf(char* th, char* tl, int off, float4 v) {
    __nv_bfloat16 hx = __float2bfloat16(v.x);
    __nv_bfloat16 hy = __float2bfloat16(v.y);
    __nv_bfloat16 hz = __float2bfloat16(v.z);
    __nv_bfloat16 hw = __float2bfloat16(v.w);
    __nv_bfloat162 h01, h23;
    h01.x = hx; h01.y = hy; h23.x = hz; h23.y = hw;
    __nv_bfloat162 l01, l23;
    l01.x = __float2bfloat16(v.x - __bfloat162float(hx));
    l01.y = __float2bfloat16(v.y - __bfloat162float(hy));
    l23.x = __float2bfloat16(v.z - __bfloat162float(hz));
    l23.y = __float2bfloat16(v.w - __bfloat162float(hw));
    uint2 hh, ll;
    hh.x = *(uint32_t*)&h01; hh.y = *(uint32_t*)&h23;
    ll.x = *(uint32_t*)&l01; ll.y = *(uint32_t*)&l23;
    *(uint2*)(th + off) = hh;
    *(uint2*)(tl + off) = ll;
}

__device__ __forceinline__ void mma16(float* c, const uint32_t* a, const uint32_t* b) {
    asm volatile(
        "mma.sync.aligned.m16n8k16.row.col.f32.bf16.bf16.f32 "
        "{%0,%1,%2,%3}, {%4,%5,%6,%7}, {%8,%9}, {%0,%1,%2,%3};"
        : "+f"(c[0]), "+f"(c[1]), "+f"(c[2]), "+f"(c[3])
        : "r"(a[0]), "r"(a[1]), "r"(a[2]), "r"(a[3]), "r"(b[0]), "r"(b[1]));
}

__global__ __launch_bounds__(256, 2) void proj_gemm_mma(
    const float* __restrict__ X,
    const float* __restrict__ WA,
    const float* __restrict__ WB,
    float* __restrict__ out)
{
    extern __shared__ char smem_c[];
    const int tid  = threadIdx.x;
    const int warp = tid >> 5;
    const int lane = tid & 31;
    const int g    = lane >> 2;     // groupID
    const int tg   = lane & 3;      // threadID_in_group
    const int wm   = warp & 3;      // warp row  (4 x 32 rows)
    const int wn   = warp >> 2;     // warp col  (2 x 64 cols)

    const int n0 = blockIdx.x * BN;
    const int t0 = blockIdx.y * BM;
    const float* __restrict__ Wbase = (n0 < 1024) ? (WA + (size_t)n0 * DIM)
                                                  : (WB + (size_t)(n0 - 1024) * DIM);

    const int rowL = tid >> 2;
    const int c4   = tid & 3;
    const float* aSrc0 = X     + (size_t)(t0 + rowL) * DIM + c4 * 4;
    const float* aSrc1 = aSrc0 + (size_t)64 * DIM;
    const float* bSrc0 = Wbase + (size_t)rowL        * DIM + c4 * 4;
    const float* bSrc1 = bSrc0 + (size_t)64 * DIM;
    const int o0 = rowL * PSTRB + c4 * 8;          // 4 bf16 = 8 B per quarter
    const int o1 = (rowL + 64) * PSTRB + c4 * 8;

    float acc[2][8][4];
    #pragma unroll
    for (int mi = 0; mi < 2; mi++)
        #pragma unroll
        for (int ni = 0; ni < 8; ni++)
            #pragma unroll
            for (int q = 0; q < 4; q++) acc[mi][ni][q] = 0.f;

    float4 a0 = *(const float4*)(aSrc0);
    float4 a1 = *(const float4*)(aSrc1);
    float4 b0 = *(const float4*)(bSrc0);
    float4 b1 = *(const float4*)(bSrc1);

    const int NCHUNK_G = DIM / BK;   // 64
    for (int ch = 0; ch < NCHUNK_G; ch++) {
        char* AH = smem_c + (ch & 1) * 4 * TSB + 0 * TSB;
        char* AL = smem_c + (ch & 1) * 4 * TSB + 1 * TSB;
        char* BH = smem_c + (ch & 1) * 4 * TSB + 2 * TSB;
        char* BL = smem_c + (ch & 1) * 4 * TSB + 3 * TSB;

        split_sts_bf(AH, AL, o0, a0);
        split_sts_bf(AH, AL, o1, a1);
        split_sts_bf(BH, BL, o0, b0);
        split_sts_bf(BH, BL, o1, b1);
        __syncthreads();

        if (ch < NCHUNK_G - 1) {
            const int k1 = (ch + 1) * BK;
            a0 = *(const float4*)(aSrc0 + k1);
            a1 = *(const float4*)(aSrc1 + k1);
            b0 = *(const float4*)(bSrc0 + k1);
            b1 = *(const float4*)(bSrc1 + k1);
        }

        // fragment loads: m16n8k16, a0=(g,2tg) a1=(g+8,2tg) a2=(g,2tg+8) a3=(g+8,2tg+8)
        uint32_t ah[2][4], al[2][4];
        #pragma unroll
        for (int mi = 0; mi < 2; mi++) {
            const int ra = (wm * 32 + mi * 16 + g) * PSTRB + tg * 4;
            ah[mi][0] = *(const uint32_t*)(AH + ra);
            ah[mi][1] = *(const uint32_t*)(AH + ra + 8 * PSTRB);
            ah[mi][2] = *(const uint32_t*)(AH + ra + 16);
            ah[mi][3] = *(const uint32_t*)(AH + ra + 8 * PSTRB + 16);
            al[mi][0] = *(const uint32_t*)(AL + ra);
            al[mi][1] = *(const uint32_t*)(AL + ra + 8 * PSTRB);
            al[mi][2] = *(const uint32_t*)(AL + ra + 16);
            al[mi][3] = *(const uint32_t*)(AL + ra + 8 * PSTRB + 16);
        }
        uint32_t bh[8][2], bl[8][2];
        #pragma unroll
        for (int ni = 0; ni < 8; ni++) {
            const int rb = (wn * 64 + ni * 8 + g) * PSTRB + tg * 4;
            bh[ni][0] = *(const uint32_t*)(BH + rb);
            bh[ni][1] = *(const uint32_t*)(BH + rb + 16);
            bl[ni][0] = *(const uint32_t*)(BL + rb);
            bl[ni][1] = *(const uint32_t*)(BL + rb + 16);
        }

        #pragma unroll
        for (int mi = 0; mi < 2; mi++)
            #pragma unroll
            for (int ni = 0; ni < 8; ni++)
                mma16(acc[mi][ni], ah[mi], bh[ni]);   // hh
        #pragma unroll
        for (int mi = 0; mi < 2; mi++)
            #pragma unroll
            for (int ni = 0; ni < 8; ni++)
                mma16(acc[mi][ni], ah[mi], bl[ni]);   // hl
        #pragma unroll
        for (int mi = 0; mi < 2; mi++)
            #pragma unroll
            for (int ni = 0; ni < 8; ni++)
                mma16(acc[mi][ni], al[mi], bh[ni]);   // lh
        __syncthreads();   // readers done before this buffer is re-stored at ch+2
    }

    #pragma unroll
    for (int mi = 0; mi < 2; mi++) {
        const int row = t0 + wm * 32 + mi * 16 + g;
        #pragma unroll
        for (int ni = 0; ni < 8; ni++) {
            const int col = n0 + wn * 64 + ni * 8 + tg * 2;
            *(float2*)(out + (size_t)row * NPROJ + col)
                = make_float2(acc[mi][ni][0], acc[mi][ni][1]);
            *(float2*)(out + (size_t)(row + 8) * NPROJ + col)
                = make_float2(acc[mi][ni][2], acc[mi][ni][3]);
        }
    }
}

// ---------------------------------------------------------------------------
// Kernel 2: fused argmin + gather-dot + output — unchanged from R16 (294 us).
// REDUX argmin + margin-gated exact-fp32 refine (TH covers bf16x3 error 40x).
// ---------------------------------------------------------------------------
#define GTOK 8
#define FUSE_SMEM (GTOK * NPROJ * 4)   // 64 KB dynamic
#define REFINE_TH 0.002f

__device__ __forceinline__ unsigned ord_f32(float f) {
    unsigned b = __float_as_uint(f);
    return (b & 0x80000000u) ? ~b : (b | 0x80000000u);  // monotonic map
}

__device__ __forceinline__ float inv_ord(unsigned u) {
    unsigned b = (u & 0x80000000u) ? (u ^ 0x80000000u) : ~u;
    return __uint_as_float(b);
}

__global__ __launch_bounds__(256) void fuse_kernel(
    const float* __restrict__ x,
    const float* __restrict__ proj,
    const float* __restrict__ W_A_, const float* __restrict__ W_B_,
    const float* __restrict__ emb_A, const float* __restrict__ vals_A,
    const float* __restrict__ emb_B, const float* __restrict__ vals_B,
    float* __restrict__ out)
{
    extern __shared__ float proj_s[];            // GTOK*2048 floats
    __shared__ float sA[GTOK * NCB];
    __shared__ float tb[GTOK * NR];
    __shared__ int   idxA[GTOK * NCB];
    __shared__ int   idxB[GTOK * NCB];

    const int tid  = threadIdx.x;
    const int warp = tid >> 5;
    const int lane = tid & 31;
    const int tok0 = blockIdx.x * GTOK;

    // ---- stage proj via cp.async ----
    {
        const float* src = proj + (size_t)tok0 * NPROJ;
        unsigned sdst = (unsigned)__cvta_generic_to_shared(proj_s);
        #pragma unroll
        for (int i = tid; i < GTOK * NPROJ / 4; i += 256) {
            asm volatile("cp.async.cg.shared.global [%0], [%1], 16;"
                         :: "r"(sdst + i * 16), "l"(src + i * 4));
        }
        asm volatile("cp.async.commit_group;");
        asm volatile("cp.async.wait_group 0;");
    }
    __syncthreads();

    // ---- distance + argmin: 128 (branch, codebook) pairs over 8 warps ----
    for (int pair = warp; pair < 2 * NCB; pair += 8) {
        const int br = pair >> 6;
        const int c  = pair & 63;
        const float* emb = br ? emb_B : emb_A;
        float e0[KD], e1[KD];
        {
            const float4* r0 = (const float4*)(emb + ((size_t)c * NP + lane) * KD);
            const float4* r1 = r0 + 32 * KD / 4;
            #pragma unroll
            for (int q = 0; q < 4; q++) {
                float4 v0 = __ldg(r0 + q), v1 = __ldg(r1 + q);
                e0[q*4+0]=v0.x; e0[q*4+1]=v0.y; e0[q*4+2]=v0.z; e0[q*4+3]=v0.w;
                e1[q*4+0]=v1.x; e1[q*4+1]=v1.y; e1[q*4+2]=v1.z; e1[q*4+3]=v1.w;
            }
        }
        float ee0 = 0.f, ee1 = 0.f;
        #pragma unroll
        for (int k = 0; k < KD; k++) { ee0 = fmaf(e0[k], e0[k], ee0); ee1 = fmaf(e1[k], e1[k], ee1); }

        #pragma unroll
        for (int g2 = 0; g2 < GTOK; g2++) {
            const float4* pr = (const float4*)(proj_s + g2 * NPROJ + br * 1024 + c * KD);
            float p[KD];
            #pragma unroll
            for (int q = 0; q < 4; q++) {
                float4 v = pr[q];   // broadcast LDS.128
                p[q*4+0]=v.x; p[q*4+1]=v.y; p[q*4+2]=v.z; p[q*4+3]=v.w;
            }
            float pp = 0.f, d0 = 0.f, d1 = 0.f;
            #pragma unroll
            for (int k = 0; k < KD; k++) {
                pp = fmaf(p[k], p[k], pp);
                d0 = fmaf(p[k], e0[k], d0);
                d1 = fmaf(p[k], e1[k], d1);
            }
            float s0 = (pp - 2.0f * d0) + ee0;
            float s1 = (pp - 2.0f * d1) + ee1;

            // 32-bit packed lexicographic min via REDUX
            unsigned q0 = (ord_f32(s0) & 0xFFFFFFC0u) | (unsigned)lane;
            unsigned q1 = (ord_f32(s1) & 0xFFFFFFC0u) | (unsigned)(lane + 32);
            unsigned qm = (q1 < q0) ? q1 : q0;
            qm = __reduce_min_sync(0xffffffffu, qm);

            // gate: any non-winner score within TH of the (rounded-down) min?
            const float smin = inv_ord(qm & 0xFFFFFFC0u);
            const int winner = (int)(qm & 63u);
            bool c0 = (s0 - smin < REFINE_TH) && (lane != winner);
            bool c1 = (s1 - smin < REFINE_TH) && (lane + 32 != winner);
            unsigned need = __ballot_sync(0xffffffffu, c0) | __ballot_sync(0xffffffffu, c1);

            int result = winner;
            if (need) {
                // exact fp32 refine: recompute 16-dim projection x . W[c]
                // lanes 2k,2k+1 jointly compute proj_k
                const float* wrow = (br ? W_B_ : W_A_)
                                  + ((size_t)c * KD + (lane >> 1)) * DIM;
                const float* xrow = x + (size_t)(tok0 + g2) * DIM;
                float acc0 = 0.f, acc1 = 0.f;
                #pragma unroll 2
                for (int d = (lane & 1) * 4; d < DIM; d += 16) {
                    float4 wv = __ldg((const float4*)(wrow + d));
                    float4 xv = *(const float4*)(xrow + d);
                    float4 wv2 = __ldg((const float4*)(wrow + d + 8));
                    float4 xv2 = *(const float4*)(xrow + d + 8);
                    acc0 = fmaf(wv.x, xv.x, acc0);
                    acc0 = fmaf(wv.y, xv.y, acc0);
                    acc0 = fmaf(wv.z, xv.z, acc0);
                    acc0 = fmaf(wv.w, xv.w, acc0);
                    acc1 = fmaf(wv2.x, xv2.x, acc1);
                    acc1 = fmaf(wv2.y, xv2.y, acc1);
                    acc1 = fmaf(wv2.z, xv2.z, acc1);
                    acc1 = fmaf(wv2.w, xv2.w, acc1);
                }
                float accp = acc0 + acc1;
                accp += __shfl_xor_sync(0xffffffffu, accp, 1);
                float pr2[KD];
                #pragma unroll
                for (int k = 0; k < KD; k++)
                    pr2[k] = __shfl_sync(0xffffffffu, accp, k * 2);
                float pp2 = 0.f, d0r = 0.f, d1r = 0.f;
                #pragma unroll
                for (int k = 0; k < KD; k++) {
                    pp2 = fmaf(pr2[k], pr2[k], pp2);
                    d0r = fmaf(pr2[k], e0[k], d0r);
                    d1r = fmaf(pr2[k], e1[k], d1r);
                }
                float r0s = (pp2 - 2.0f * d0r) + ee0;
                float r1s = (pp2 - 2.0f * d1r) + ee1;
                unsigned long long rk0 = ((unsigned long long)ord_f32(r0s) << 6) | (unsigned)lane;
                unsigned long long rk1 = ((unsigned long long)ord_f32(r1s) << 6) | (unsigned)(lane + 32);
                unsigned long long key = (rk1 < rk0) ? rk1 : rk0;
                #pragma unroll
                for (int off = 16; off > 0; off >>= 1) {
                    unsigned long long o = __shfl_xor_sync(0xffffffffu, key, off);
                    if (o < key) key = o;
                }
                result = (int)(key & 63u);
            }

            if (lane == 0) (br ? idxB : idxA)[g2 * NCB + c] = result;
        }
    }
    __syncthreads();

    // ---- sA: warp per (token, chunk); x-chunk in regs, 8x reuse over c ----
    for (int task = warp; task < GTOK * 8; task += 8) {
        const int g2 = task >> 3, chunk = task & 7;
        float4 xr = *(const float4*)(x + (size_t)(tok0 + g2) * DIM + chunk * MV + lane * 4);
        float acc[8];
        #pragma unroll
        for (int ci = 0; ci < 8; ci++) {
            const int c = ci * 8 + chunk;
            const int id = idxA[g2 * NCB + c];
            float4 vr = __ldg((const float4*)(vals_A + ((size_t)c * NP + id) * MV) + lane);
            acc[ci] = xr.x*vr.x + xr.y*vr.y + xr.z*vr.z + xr.w*vr.w;
        }
        #pragma unroll
        for (int off = 16; off > 0; off >>= 1)
            #pragma unroll
            for (int ci = 0; ci < 8; ci++)
                acc[ci] += __shfl_xor_sync(0xffffffffu, acc[ci], off);
        if (lane == 0) {
            #pragma unroll
            for (int ci = 0; ci < 8; ci++)
                sA[g2 * NCB + ci * 8 + chunk] = acc[ci];
        }
    }
    __syncthreads();

    // ---- t[g][r] = sum of 8 consecutive s ----
    if (tid < GTOK * NR) {
        const int g2 = tid >> 3, r = tid & 7;
        float acc = 0.f;
        #pragma unroll
        for (int i = 0; i < 8; i++) acc += sA[g2 * NCB + r * 8 + i];
        tb[g2 * NR + r] = acc;
    }
    __syncthreads();

    // ---- out[token][h*128+m] = sum_r t[r] * vals_B[8r+h, idxB[8r+h], m] ----
    for (int g2 = 0; g2 < GTOK; g2++) {
        float tr[NR];
        #pragma unroll
        for (int r = 0; r < NR; r++) tr[r] = tb[g2 * NR + r];
        float* orow = out + (size_t)(tok0 + g2) * DIM;
        #pragma unroll
        for (int j = 0; j < 4; j++) {
            const int d = tid + 256 * j;
            const int h = d >> 7, m = d & 127;
            float acc = 0.f;
            #pragma unroll
            for (int r = 0; r < NR; r++) {
                const int c = 8 * r + h;
                acc = fmaf(tr[r],
                           __ldg(vals_B + ((size_t)c * NP + idxB[g2 * NCB + c]) * MV + m),
                           acc);
            }
            orow[d] = acc;
        }
    }
}

// ---------------------------------------------------------------------------
extern "C" void kernel_launch(void* const* d_in, const int* in_sizes, int n_in,
                              void* d_out, int out_size)
{
    (void)in_sizes; (void)n_in; (void)out_size;
    const float* x      = (const float*)d_in[0];
    const float* W_A    = (const float*)d_in[1];
    const float* emb_A  = (const float*)d_in[2];
    const float* vals_A = (const float*)d_in[3];
    const float* W_B    = (const float*)d_in[4];
    const float* emb_B  = (const float*)d_in[5];
    const float* vals_B = (const float*)d_in[6];
    float* out = (float*)d_out;

    float* proj;
    cudaGetSymbolAddress((void**)&proj, g_proj);

    static bool attr_set = false;
    if (!attr_set) {
        cudaFuncSetAttribute(proj_gemm_mma,
                             cudaFuncAttributeMaxDynamicSharedMemorySize, GEMM_SMEM);
        cudaFuncSetAttribute(fuse_kernel,
                             cudaFuncAttributeMaxDynamicSharedMemorySize, FUSE_SMEM);
        attr_set = true;
    }

    dim3 gg(NPROJ / BN, TOK / BM);   // (16, 64)
    proj_gemm_mma<<<gg, 256, GEMM_SMEM>>>(x, W_A, W_B, proj);
    fuse_kernel<<<TOK / GTOK, 256, FUSE_SMEM>>>(x, proj, W_A, W_B,
                                                emb_A, vals_A, emb_B, vals_B, out);
}